// round 7
// baseline (speedup 1.0000x reference)
#include <cuda_runtime.h>
#include <cuda_bf16.h>
#include <cstdint>

// ---------------------------------------------------------------------------
// Problem constants
// ---------------------------------------------------------------------------
#define EPSF 1e-8f

constexpr int NQ = 8192;     // queries
constexpr int NK = 524288;   // keys
constexpr int D  = 128;      // head_dim
constexpr int NF = 64;       // num_freqs
constexpr int NB = 128;      // num_bins
constexpr int DT = 192;      // D + NF  (GEMM K-dimension, in bytes for int8)

constexpr int SB = 208;                    // byte stride per row (conflict-free ldmatrix)
constexpr int WBUF = 128 * SB;             // 26,624 B per hi/lo buffer

// ---------------------------------------------------------------------------
// Device scratch (no allocations allowed)
// ---------------------------------------------------------------------------
__device__ __align__(16) unsigned char g_Whi8[WBUF];
__device__ __align__(16) unsigned char g_Wlo8[WBUF];
__device__ float2 g_rpq[NF * NB];    // rotated probe pairs, [f][b]
__device__ float  g_effw[NF * NB];   // -softplus(q_weights_raw), [f][b]
__device__ float  g_qmw[NF * NB];    // q_magnitude_weights, [f][b]

// ---------------------------------------------------------------------------
// Helpers
// ---------------------------------------------------------------------------
__device__ __forceinline__ float sqrt_approx(float x) {
    float y;
    asm("sqrt.approx.f32 %0, %1;" : "=f"(y) : "f"(x));
    return y;
}

// fixed-point split: round(x*2048) = 128*h + l, h in [-127,127], l in [-64,64]
__device__ __forceinline__ void q8(float x, int& h, int& l) {
    int a = __float2int_rn(x * 2048.0f);
    a = max(-16256, min(16256, a));
    h = (a + 64) >> 7;
    l = a - (h << 7);
}

__device__ __forceinline__ uint32_t pack4(int b0, int b1, int b2, int b3) {
    return (uint32_t)(b0 & 255) | ((uint32_t)(b1 & 255) << 8) |
           ((uint32_t)(b2 & 255) << 16) | ((uint32_t)b3 << 24);
}

__device__ __forceinline__ uint32_t smem_u32(const void* p) {
    uint32_t a;
    asm("{ .reg .u64 t; cvta.to.shared.u64 t, %1; cvt.u32.u64 %0, t; }" : "=r"(a) : "l"(p));
    return a;
}

__device__ __forceinline__ void ldm4(uint32_t* r, uint32_t addr) {
    asm volatile("ldmatrix.sync.aligned.m8n8.x4.shared.b16 {%0,%1,%2,%3}, [%4];"
        : "=r"(r[0]), "=r"(r[1]), "=r"(r[2]), "=r"(r[3]) : "r"(addr));
}

__device__ __forceinline__ void imma16832(int* c, const uint32_t* a, const uint32_t* b) {
    asm volatile("mma.sync.aligned.m16n8k32.row.col.s32.s8.s8.s32 "
        "{%0,%1,%2,%3}, {%4,%5,%6,%7}, {%8,%9}, {%0,%1,%2,%3};"
        : "+r"(c[0]), "+r"(c[1]), "+r"(c[2]), "+r"(c[3])
        : "r"(a[0]), "r"(a[1]), "r"(a[2]), "r"(a[3]), "r"(b[0]), "r"(b[1]));
}

__device__ __forceinline__ void cpasync16(uint32_t saddr, const void* g) {
    asm volatile("cp.async.cg.shared.global [%0], [%1], 16;" :: "r"(saddr), "l"(g));
}
#define CP_COMMIT() asm volatile("cp.async.commit_group;" ::: "memory")
#define CP_WAIT0()  asm volatile("cp.async.wait_group 0;" ::: "memory")

// ---------------------------------------------------------------------------
// Prep kernel: one block per bin, 64 threads (one per freq)
// ---------------------------------------------------------------------------
__global__ void prep_kernel(const float* __restrict__ angles,
                            const float* __restrict__ probes,
                            const float* __restrict__ kmw,
                            const float* __restrict__ qraw,
                            const float* __restrict__ qmw)
{
    __shared__ float red[2];
    const int b = blockIdx.x;
    const int f = threadIdx.x;   // 0..63

    float p0 = probes[b * D + 2 * f];
    float p1 = probes[b * D + 2 * f + 1];
    float s = fmaf(p0, p0, p1 * p1);
    #pragma unroll
    for (int o = 16; o; o >>= 1) s += __shfl_xor_sync(0xffffffffu, s, o);
    if ((f & 31) == 0) red[f >> 5] = s;
    __syncthreads();
    float inv = 1.0f / (sqrtf(red[0] + red[1]) + EPSF);
    p0 *= inv; p1 *= inv;

    float a  = angles[f];
    float ca = cosf(a), sa = sinf(a);
    float r0 = p0 * ca - p1 * sa;
    float r1 = p0 * sa + p1 * ca;
    g_rpq[f * NB + b] = make_float2(r0, r1);

    int h0, l0, h1, l1;
    q8(r0, h0, l0); q8(r1, h1, l1);
    g_Whi8[b * SB + 2 * f]     = (unsigned char)h0;
    g_Whi8[b * SB + 2 * f + 1] = (unsigned char)h1;
    g_Wlo8[b * SB + 2 * f]     = (unsigned char)l0;
    g_Wlo8[b * SB + 2 * f + 1] = (unsigned char)l1;

    int hw, lw;
    q8(kmw[b * NF + f], hw, lw);
    g_Whi8[b * SB + D + f] = (unsigned char)hw;
    g_Wlo8[b * SB + D + f] = (unsigned char)lw;

    if (f < 16) {  // zero pad bytes 192..207
        g_Whi8[b * SB + 192 + f] = 0;
        g_Wlo8[b * SB + 192 + f] = 0;
    }

    float x  = qraw[b * NF + f];
    float sp = fmaxf(x, 0.0f) + log1pf(expf(-fabsf(x)));
    g_effw[f * NB + b] = -sp;
    g_qmw[f * NB + b]  = qmw[b * NF + f];
}

// ---------------------------------------------------------------------------
// K path: int8 IMMA (m16n8k32) GEMM, 3-term fixed-point emulation.
// out[row][bin] = (acc1/256 + acc2/32768) + bias
// 512 threads, 16 warps in 4(M)x4(N), 32x32 per warp.
// cp.async double-buffers the raw f32 tile under the IMMA loop.
// ---------------------------------------------------------------------------
constexpr int TILE_M   = 128;
constexpr int KTHREADS = 512;
constexpr int TILES    = 4;
constexpr int FPT      = (TILE_M * (D / 4)) / KTHREADS;   // float4 per thread = 8

constexpr int OFF_WHI   = 0;
constexpr int OFF_WLO   = OFF_WHI + WBUF;      //  26,624
constexpr int OFF_AHI   = OFF_WLO + WBUF;      //  53,248
constexpr int OFF_ALO   = OFF_AHI + WBUF;      //  79,872
constexpr int OFF_STAGE = 106496;              //  64KB raw f32 tile (16-aligned)
constexpr int OFF_BIAS  = OFF_STAGE + 65536;   // 172,032
constexpr int SMEMK_SZ  = OFF_BIAS + 512;      // 172,544

__global__ void __launch_bounds__(KTHREADS, 1)
kpath_kernel(const float* __restrict__ Kmat,
             const float* __restrict__ kbias,
             float* __restrict__ out)
{
    extern __shared__ char smc[];
    const uint32_t base = smem_u32(smc);
    float* sBias = reinterpret_cast<float*>(smc + OFF_BIAS);
    const float4* stage4 = reinterpret_cast<const float4*>(smc + OFF_STAGE);

    const int tid  = threadIdx.x;
    const int lane = tid & 31;
    const int wid  = tid >> 5;
    const int wm   = (wid & 3) * 32;    // warp M offset
    const int wn   = (wid >> 2) * 32;   // warp N offset

    // W hi/lo -> smem (layout already final)
    {
        const int4* gh = reinterpret_cast<const int4*>(g_Whi8);
        const int4* gl = reinterpret_cast<const int4*>(g_Wlo8);
        int4* sh = reinterpret_cast<int4*>(smc + OFF_WHI);
        int4* sl = reinterpret_cast<int4*>(smc + OFF_WLO);
        for (int i = tid; i < WBUF / 16; i += KTHREADS) { sh[i] = gh[i]; sl[i] = gl[i]; }
    }
    if (tid < NB) sBias[tid] = kbias[tid];

    // ldmatrix lane base addresses (byte layout, SB=208 stride)
    // A x4 frag i: m0 rows 0-7 @kB, m1 rows 8-15 @kB, m2 rows 0-7 @kB+16, m3 rows 8-15 @kB+16
    const uint32_t aAddr = base + OFF_AHI
        + (uint32_t)(wm + (lane & 7) + ((lane >> 3) & 1) * 8) * SB
        + ((lane >> 4) & 1) * 16;
    const uint32_t aHiA = aAddr;
    const uint32_t aLoA = aAddr + (OFF_ALO - OFF_AHI);
    // B x4 frag jj: m0 bins 0-7 @kB, m1 bins 0-7 @kB+16, m2 bins 8-15 @kB, m3 bins 8-15 @kB+16
    const uint32_t bAddr = base + OFF_WHI
        + (uint32_t)(wn + (lane & 7) + ((lane >> 4) & 1) * 8) * SB
        + ((lane >> 3) & 1) * 16;
    const uint32_t bHiA = bAddr;
    const uint32_t bLoA = bAddr + (OFF_WLO - OFF_WHI);

    constexpr uint32_t MSTEP = 16 * SB;   // 16 rows in bytes

    // Prologue: cp.async raw tile 0 into stage
    {
        const char* g = reinterpret_cast<const char*>(Kmat)
                      + (size_t)(blockIdx.x * TILES) * TILE_M * D * 4;
        #pragma unroll
        for (int it = 0; it < FPT; it++)
            cpasync16(base + OFF_STAGE + (it * KTHREADS + tid) * 16,
                      g + (it * KTHREADS + tid) * 16);
        CP_COMMIT();
    }

    for (int t = 0; t < TILES; t++) {
        const int rowBase = (blockIdx.x * TILES + t) * TILE_M;

        CP_WAIT0();
        __syncthreads();   // stage ready; prior tile's ldmatrix reads done

        // ---- Convert stage f32 -> A hi/lo int8 (quantize + magnitudes)
        #pragma unroll
        for (int it = 0; it < FPT; it++) {
            const int i = it * KTHREADS + tid;
            const int row = i >> 5, c4 = i & 31;
            float4 v = stage4[i];
            int h0, l0, h1, l1, h2, l2, h3, l3;
            q8(v.x, h0, l0); q8(v.y, h1, l1);
            q8(v.z, h2, l2); q8(v.w, h3, l3);
            const int eb = row * SB + 4 * c4;
            *reinterpret_cast<uint32_t*>(smc + OFF_AHI + eb) = pack4(h0, h1, h2, h3);
            *reinterpret_cast<uint32_t*>(smc + OFF_ALO + eb) = pack4(l0, l1, l2, l3);
            float m0 = sqrt_approx(fmaf(v.x, v.x, fmaf(v.y, v.y, EPSF)));
            float m1 = sqrt_approx(fmaf(v.z, v.z, fmaf(v.w, v.w, EPSF)));
            int mh0, ml0, mh1, ml1;
            q8(m0, mh0, ml0); q8(m1, mh1, ml1);
            const int em = row * SB + D + 2 * c4;
            *reinterpret_cast<uint16_t*>(smc + OFF_AHI + em) =
                (uint16_t)((mh0 & 255) | ((mh1 & 255) << 8));
            *reinterpret_cast<uint16_t*>(smc + OFF_ALO + em) =
                (uint16_t)((ml0 & 255) | ((ml1 & 255) << 8));
        }
        __syncthreads();   // A ready, stage consumed

        // ---- cp.async next raw tile (completes under the IMMA loop)
        if (t + 1 < TILES) {
            const char* g = reinterpret_cast<const char*>(Kmat)
                          + (size_t)(rowBase + TILE_M) * D * 4;
            #pragma unroll
            for (int it = 0; it < FPT; it++)
                cpasync16(base + OFF_STAGE + (it * KTHREADS + tid) * 16,
                          g + (it * KTHREADS + tid) * 16);
            CP_COMMIT();
        }

        // ---- IMMA mainloop: 6 k-chunks (k=32 bytes), 2m x 4n positions x 3 terms
        int c1[2][4][4], c2[2][4][4];
        #pragma unroll
        for (int i = 0; i < 2; i++)
            #pragma unroll
            for (int j = 0; j < 4; j++)
                #pragma unroll
                for (int r = 0; r < 4; r++) { c1[i][j][r] = 0; c2[i][j][r] = 0; }

        #pragma unroll
        for (int kc = 0; kc < DT / 32; kc++) {
            const uint32_t kB = (uint32_t)kc * 32;
            uint32_t ah[2][4], al[2][4], bh[2][4], bl[2][4];
            #pragma unroll
            for (int i = 0; i < 2; i++) {
                ldm4(ah[i], aHiA + i * MSTEP + kB);
                ldm4(al[i], aLoA + i * MSTEP + kB);
            }
            #pragma unroll
            for (int jj = 0; jj < 2; jj++) {
                ldm4(bh[jj], bHiA + jj * MSTEP + kB);
                ldm4(bl[jj], bLoA + jj * MSTEP + kB);
            }
            #pragma unroll
            for (int i = 0; i < 2; i++) {
                #pragma unroll
                for (int j = 0; j < 4; j++) {
                    const uint32_t* BH = &bh[j >> 1][(j & 1) * 2];
                    const uint32_t* BL = &bl[j >> 1][(j & 1) * 2];
                    imma16832(c1[i][j], ah[i], BH);
                    imma16832(c2[i][j], ah[i], BL);
                    imma16832(c2[i][j], al[i], BH);
                }
            }
        }

        // ---- Epilogue: combine scales + bias, STG.64
        constexpr float S1 = 1.0f / 256.0f;
        constexpr float S2 = 1.0f / 32768.0f;
        float2* out2 = reinterpret_cast<float2*>(out);
        const int r0 = rowBase + wm + (lane >> 2);
        #pragma unroll
        for (int j = 0; j < 4; j++) {
            const int col = wn + j * 8 + (lane & 3) * 2;
            const float bx = sBias[col], by = sBias[col + 1];
            const int ch = col >> 1;
            #pragma unroll
            for (int i = 0; i < 2; i++) {
                const int row = r0 + i * 16;
                float2 v0, v1;
                v0.x = fmaf((float)c1[i][j][0], S1, fmaf((float)c2[i][j][0], S2, bx));
                v0.y = fmaf((float)c1[i][j][1], S1, fmaf((float)c2[i][j][1], S2, by));
                v1.x = fmaf((float)c1[i][j][2], S1, fmaf((float)c2[i][j][2], S2, bx));
                v1.y = fmaf((float)c1[i][j][3], S1, fmaf((float)c2[i][j][3], S2, by));
                out2[(size_t)row * (NB / 2) + ch] = v0;
                out2[(size_t)(row + 8) * (NB / 2) + ch] = v1;
            }
        }
    }
}

// ---------------------------------------------------------------------------
// Q path (unchanged)
// ---------------------------------------------------------------------------
constexpr int QTHREADS = 256;
constexpr int QPB      = 32;

__global__ void __launch_bounds__(QTHREADS, 1)
qpath_kernel(const float* __restrict__ Q,
             const float* __restrict__ qbias,
             float* __restrict__ outq)
{
    extern __shared__ float smem[];
    float2* sRP  = reinterpret_cast<float2*>(smem);      // NF*NB float2
    float* sEW   = smem + 2 * NF * NB;                   // NF*NB
    float* sMW   = sEW + NF * NB;                        // NF*NB
    float* sQn   = sMW + NF * NB;                        // QPB*D
    float* sQmag = sQn + QPB * D;                        // QPB*NF
    float* sInv  = sQmag + QPB * NF;                     // QPB
    float* sQB   = sInv + QPB;                           // NB

    const int tid = threadIdx.x;
    for (int i = tid; i < NF * NB; i += QTHREADS) {
        sRP[i] = g_rpq[i];
        sEW[i] = g_effw[i];
        sMW[i] = g_qmw[i];
    }
    if (tid < NB) sQB[tid] = qbias[tid];

    const int qbase = blockIdx.x * QPB;
    for (int i = tid; i < QPB * D; i += QTHREADS)
        sQn[i] = Q[(size_t)qbase * D + i];
    __syncthreads();

    {
        int q = tid >> 3, l8 = tid & 7;
        float s = 0.0f;
        #pragma unroll
        for (int j = 0; j < D / 8; j++) {
            float v = sQn[q * D + l8 + 8 * j];
            s = fmaf(v, v, s);
        }
        s += __shfl_down_sync(0xffffffffu, s, 4, 8);
        s += __shfl_down_sync(0xffffffffu, s, 2, 8);
        s += __shfl_down_sync(0xffffffffu, s, 1, 8);
        if (l8 == 0) sInv[q] = 1.0f / (sqrtf(s) + EPSF);
    }
    __syncthreads();
    for (int i = tid; i < QPB * D; i += QTHREADS)
        sQn[i] *= sInv[i >> 7];
    __syncthreads();
    for (int i = tid; i < QPB * NF; i += QTHREADS) {
        int q = i >> 6, f = i & 63;
        float a = sQn[q * D + 2 * f];
        float c = sQn[q * D + 2 * f + 1];
        sQmag[i] = sqrt_approx(fmaf(a, a, fmaf(c, c, EPSF)));
    }
    __syncthreads();

    const int b  = tid & 127;
    const int qg = tid >> 7;
    float acc[16];
    #pragma unroll
    for (int j = 0; j < 16; j++) acc[j] = 0.0f;

    for (int f = 0; f < NF; f++) {
        float2 rp = sRP[f * NB + b];
        float  ew = sEW[f * NB + b];
        float  mw = sMW[f * NB + b];
        #pragma unroll
        for (int j = 0; j < 16; j++) {
            int q = qg * 16 + j;
            float2 qp = *reinterpret_cast<const float2*>(sQn + q * D + 2 * f);
            float d0 = rp.x - qp.x;
            float d1 = rp.y - qp.y;
            float dist = sqrt_approx(fmaf(d0, d0, fmaf(d1, d1, EPSF)));
            acc[j] = fmaf(dist, ew, acc[j]);
            acc[j] = fmaf(sQmag[q * NF + f], mw, acc[j]);
        }
    }

    #pragma unroll
    for (int j = 0; j < 16; j++) {
        int q = qbase + qg * 16 + j;
        outq[(size_t)q * NB + b] = acc[j] + sQB[b];
    }
}

// ---------------------------------------------------------------------------
// Launch
// ---------------------------------------------------------------------------
extern "C" void kernel_launch(void* const* d_in, const int* in_sizes, int n_in,
                              void* d_out, int out_size)
{
    const float* Q      = (const float*)d_in[0];
    const float* Kmat   = (const float*)d_in[1];
    const float* angles = (const float*)d_in[2];
    const float* probes = (const float*)d_in[3];
    const float* kmw    = (const float*)d_in[4];
    const float* kbias  = (const float*)d_in[5];
    const float* qraw   = (const float*)d_in[6];
    const float* qmw    = (const float*)d_in[7];
    const float* qbias  = (const float*)d_in[8];
    float* out = (float*)d_out;

    const size_t smemQ = (size_t)(2 * NF * NB + NF * NB + NF * NB + QPB * D + QPB * NF
                                  + QPB + NB) * sizeof(float);

    cudaFuncSetAttribute(kpath_kernel, cudaFuncAttributeMaxDynamicSharedMemorySize, SMEMK_SZ);
    cudaFuncSetAttribute(qpath_kernel, cudaFuncAttributeMaxDynamicSharedMemorySize, (int)smemQ);

    prep_kernel<<<NB, NF>>>(angles, probes, kmw, qraw, qmw);
    kpath_kernel<<<NK / (TILE_M * TILES), KTHREADS, SMEMK_SZ>>>(Kmat, kbias, out);
    qpath_kernel<<<NQ / QPB, QTHREADS, smemQ>>>(Q, qbias, out + (size_t)NK * NB);
}

// round 8
// speedup vs baseline: 3.4111x; 3.4111x over previous
#include <cuda_runtime.h>
#include <cuda_fp16.h>
#include <cstdint>

// ---------------------------------------------------------------------------
// Problem constants
// ---------------------------------------------------------------------------
#define EPSF 1e-8f

constexpr int NQ = 8192;     // queries
constexpr int NK = 524288;   // keys
constexpr int D  = 128;      // head_dim
constexpr int NF = 64;       // num_freqs
constexpr int NB = 128;      // num_bins
constexpr int DT = 192;      // D + NF  (GEMM K-dimension)

constexpr int STRIDE = 200;                 // fp16 elems per row (400B -> conflict-free ldmatrix)
constexpr int WBUF_BYTES = 128 * STRIDE * 2;   // 51,200 B

// ---------------------------------------------------------------------------
// Device scratch (no allocations allowed)
// ---------------------------------------------------------------------------
__device__ __align__(16) __half g_Wh[128 * STRIDE];   // W fp16, [bin][k], stride 200
__device__ float2 g_rpq[NF * NB];    // rotated probe pairs, [f][b]
__device__ float  g_effw[NF * NB];   // -softplus(q_weights_raw), [f][b]
__device__ float  g_qmw[NF * NB];    // q_magnitude_weights, [f][b]

// ---------------------------------------------------------------------------
// Helpers
// ---------------------------------------------------------------------------
__device__ __forceinline__ float sqrt_approx(float x) {
    float y;
    asm("sqrt.approx.f32 %0, %1;" : "=f"(y) : "f"(x));
    return y;
}

__device__ __forceinline__ uint32_t packh2(float a, float b) {
    __half2 t = __floats2half2_rn(a, b);
    return *reinterpret_cast<uint32_t*>(&t);
}

__device__ __forceinline__ uint32_t smem_u32(const void* p) {
    uint32_t a;
    asm("{ .reg .u64 t; cvta.to.shared.u64 t, %1; cvt.u32.u64 %0, t; }" : "=r"(a) : "l"(p));
    return a;
}

__device__ __forceinline__ void ldm4(uint32_t* r, uint32_t addr) {
    asm volatile("ldmatrix.sync.aligned.m8n8.x4.shared.b16 {%0,%1,%2,%3}, [%4];"
        : "=r"(r[0]), "=r"(r[1]), "=r"(r[2]), "=r"(r[3]) : "r"(addr));
}

__device__ __forceinline__ void mma16816(float* c, const uint32_t* a, const uint32_t* b) {
    asm volatile("mma.sync.aligned.m16n8k16.row.col.f32.f16.f16.f32 "
        "{%0,%1,%2,%3}, {%4,%5,%6,%7}, {%8,%9}, {%0,%1,%2,%3};"
        : "+f"(c[0]), "+f"(c[1]), "+f"(c[2]), "+f"(c[3])
        : "r"(a[0]), "r"(a[1]), "r"(a[2]), "r"(a[3]), "r"(b[0]), "r"(b[1]));
}

__device__ __forceinline__ void cpasync16(uint32_t saddr, const void* g) {
    asm volatile("cp.async.cg.shared.global [%0], [%1], 16;" :: "r"(saddr), "l"(g));
}
#define CP_COMMIT() asm volatile("cp.async.commit_group;" ::: "memory")
#define CP_WAIT0()  asm volatile("cp.async.wait_group 0;" ::: "memory")

// ---------------------------------------------------------------------------
// Prep kernel: one block per bin, 64 threads (one per freq)
// ---------------------------------------------------------------------------
__global__ void prep_kernel(const float* __restrict__ angles,
                            const float* __restrict__ probes,
                            const float* __restrict__ kmw,
                            const float* __restrict__ qraw,
                            const float* __restrict__ qmw)
{
    __shared__ float red[2];
    const int b = blockIdx.x;
    const int f = threadIdx.x;   // 0..63

    float p0 = probes[b * D + 2 * f];
    float p1 = probes[b * D + 2 * f + 1];
    float s = fmaf(p0, p0, p1 * p1);
    #pragma unroll
    for (int o = 16; o; o >>= 1) s += __shfl_xor_sync(0xffffffffu, s, o);
    if ((f & 31) == 0) red[f >> 5] = s;
    __syncthreads();
    float inv = 1.0f / (sqrtf(red[0] + red[1]) + EPSF);
    p0 *= inv; p1 *= inv;

    float a  = angles[f];
    float ca = cosf(a), sa = sinf(a);
    float r0 = p0 * ca - p1 * sa;
    float r1 = p0 * sa + p1 * ca;
    g_rpq[f * NB + b] = make_float2(r0, r1);

    // W[bin][k], stride 200: k = 2f,2f+1 <- rotated pair; k = 128+f <- kmw
    g_Wh[b * STRIDE + 2 * f]     = __float2half_rn(r0);
    g_Wh[b * STRIDE + 2 * f + 1] = __float2half_rn(r1);
    g_Wh[b * STRIDE + D + f]     = __float2half_rn(kmw[b * NF + f]);
    if (f < 8) g_Wh[b * STRIDE + 192 + f] = __float2half_rn(0.f);

    float x  = qraw[b * NF + f];
    float sp = fmaxf(x, 0.0f) + log1pf(expf(-fabsf(x)));
    g_effw[f * NB + b] = -sp;
    g_qmw[f * NB + b]  = qmw[b * NF + f];
}

// ---------------------------------------------------------------------------
// K path: single-pass fp16 mma.sync GEMM.
// out[row][bin] = sum_k A[row][k] * W[bin][k] + bias[bin]
//   A[:,0:128] = K row (fp16), A[:,128:192] = per-pair magnitudes (fp16)
// 512 threads, 16 warps in 4(M)x4(N), 32x32 per warp.
// cp.async double-buffers the raw f32 tile under the MMA loop.
// ---------------------------------------------------------------------------
constexpr int TILE_M   = 128;
constexpr int KTHREADS = 512;
constexpr int TILES    = 4;
constexpr int FPT      = (TILE_M * (D / 4)) / KTHREADS;   // float4 per thread = 8

constexpr int OFF_WH    = 0;
constexpr int OFF_A     = OFF_WH + WBUF_BYTES;   //  51,200
constexpr int OFF_STAGE = OFF_A + WBUF_BYTES;    // 102,400 (64KB raw f32 tile)
constexpr int OFF_BIAS  = OFF_STAGE + 65536;     // 167,936
constexpr int SMEMK_SZ  = OFF_BIAS + 512;        // 168,448

__global__ void __launch_bounds__(KTHREADS, 1)
kpath_kernel(const float* __restrict__ Kmat,
             const float* __restrict__ kbias,
             float* __restrict__ out)
{
    extern __shared__ char smc[];
    const uint32_t base = smem_u32(smc);
    float* sBias = reinterpret_cast<float*>(smc + OFF_BIAS);
    const float4* stage4 = reinterpret_cast<const float4*>(smc + OFF_STAGE);

    const int tid  = threadIdx.x;
    const int lane = tid & 31;
    const int wid  = tid >> 5;
    const int wm   = (wid & 3) * 32;    // warp M offset
    const int wn   = (wid >> 2) * 32;   // warp N offset

    // W -> smem (layout already final)
    {
        const int4* gw = reinterpret_cast<const int4*>(g_Wh);
        int4* sw = reinterpret_cast<int4*>(smc + OFF_WH);
        for (int i = tid; i < WBUF_BYTES / 16; i += KTHREADS) sw[i] = gw[i];
    }
    if (tid < NB) sBias[tid] = kbias[tid];

    // ldmatrix lane base addresses (constant across chunks)
    const int aRow = wm + (lane & 7) + ((lane >> 3) & 1) * 8;
    const int aK   = ((lane >> 4) & 1) * 8;
    const uint32_t aA = base + OFF_A + (uint32_t)(aRow * STRIDE + aK) * 2;
    const int bRow = wn + (lane & 7) + ((lane >> 4) & 1) * 8;
    const int bK   = ((lane >> 3) & 1) * 8;
    const uint32_t bA = base + OFF_WH + (uint32_t)(bRow * STRIDE + bK) * 2;

    constexpr uint32_t MSTEP = 16 * STRIDE * 2;   // 16 rows in bytes

    // Prologue: cp.async raw tile 0 into stage
    {
        const char* g = reinterpret_cast<const char*>(Kmat)
                      + (size_t)(blockIdx.x * TILES) * TILE_M * D * 4;
        #pragma unroll
        for (int it = 0; it < FPT; it++)
            cpasync16(base + OFF_STAGE + (it * KTHREADS + tid) * 16,
                      g + (it * KTHREADS + tid) * 16);
        CP_COMMIT();
    }

    for (int t = 0; t < TILES; t++) {
        const int rowBase = (blockIdx.x * TILES + t) * TILE_M;

        CP_WAIT0();
        __syncthreads();   // stage ready; prior tile's ldmatrix reads done

        // ---- Convert stage f32 -> A fp16 (+ magnitudes)
        #pragma unroll
        for (int it = 0; it < FPT; it++) {
            const int i = it * KTHREADS + tid;
            const int row = i >> 5, c4 = i & 31;
            float4 v = stage4[i];
            const int e0 = row * STRIDE + 4 * c4;        // even, 8B-aligned
            uint2 hv = make_uint2(packh2(v.x, v.y), packh2(v.z, v.w));
            *reinterpret_cast<uint2*>(smc + OFF_A + 2 * e0) = hv;
            float m0 = sqrt_approx(fmaf(v.x, v.x, fmaf(v.y, v.y, EPSF)));
            float m1 = sqrt_approx(fmaf(v.z, v.z, fmaf(v.w, v.w, EPSF)));
            const int em = row * STRIDE + D + 2 * c4;    // even, 4B-aligned
            *reinterpret_cast<uint32_t*>(smc + OFF_A + 2 * em) = packh2(m0, m1);
        }
        __syncthreads();   // A ready, stage consumed

        // ---- cp.async next raw tile (completes under the MMA loop)
        if (t + 1 < TILES) {
            const char* g = reinterpret_cast<const char*>(Kmat)
                          + (size_t)(rowBase + TILE_M) * D * 4;
            #pragma unroll
            for (int it = 0; it < FPT; it++)
                cpasync16(base + OFF_STAGE + (it * KTHREADS + tid) * 16,
                          g + (it * KTHREADS + tid) * 16);
            CP_COMMIT();
        }

        // ---- MMA mainloop: 12 k-chunks, 2m x 4n positions, 1 term
        float c[2][4][4];
        #pragma unroll
        for (int i = 0; i < 2; i++)
            #pragma unroll
            for (int j = 0; j < 4; j++)
                #pragma unroll
                for (int r = 0; r < 4; r++) c[i][j][r] = 0.0f;

        #pragma unroll
        for (int kc = 0; kc < DT / 16; kc++) {
            const uint32_t kB = (uint32_t)kc * 32;
            uint32_t af[2][4], bf[2][4];
            #pragma unroll
            for (int i = 0; i < 2; i++) ldm4(af[i], aA + i * MSTEP + kB);
            #pragma unroll
            for (int jj = 0; jj < 2; jj++) ldm4(bf[jj], bA + jj * MSTEP + kB);
            #pragma unroll
            for (int i = 0; i < 2; i++)
                #pragma unroll
                for (int j = 0; j < 4; j++)
                    mma16816(c[i][j], af[i], &bf[j >> 1][(j & 1) * 2]);
        }

        // ---- Epilogue: bias + STG.64 from accumulators
        float2* out2 = reinterpret_cast<float2*>(out);
        const int r0 = rowBase + wm + (lane >> 2);
        #pragma unroll
        for (int j = 0; j < 4; j++) {
            const int col = wn + j * 8 + (lane & 3) * 2;
            const float bx = sBias[col], by = sBias[col + 1];
            const int ch = col >> 1;
            #pragma unroll
            for (int i = 0; i < 2; i++) {
                const int row = r0 + i * 16;
                float2 v0 = make_float2(c[i][j][0] + bx, c[i][j][1] + by);
                float2 v1 = make_float2(c[i][j][2] + bx, c[i][j][3] + by);
                out2[(size_t)row * (NB / 2) + ch] = v0;
                out2[(size_t)(row + 8) * (NB / 2) + ch] = v1;
            }
        }
    }
}

// ---------------------------------------------------------------------------
// Q path (unchanged)
// ---------------------------------------------------------------------------
constexpr int QTHREADS = 256;
constexpr int QPB      = 32;

__global__ void __launch_bounds__(QTHREADS, 1)
qpath_kernel(const float* __restrict__ Q,
             const float* __restrict__ qbias,
             float* __restrict__ outq)
{
    extern __shared__ float smem[];
    float2* sRP  = reinterpret_cast<float2*>(smem);      // NF*NB float2
    float* sEW   = smem + 2 * NF * NB;                   // NF*NB
    float* sMW   = sEW + NF * NB;                        // NF*NB
    float* sQn   = sMW + NF * NB;                        // QPB*D
    float* sQmag = sQn + QPB * D;                        // QPB*NF
    float* sInv  = sQmag + QPB * NF;                     // QPB
    float* sQB   = sInv + QPB;                           // NB

    const int tid = threadIdx.x;
    for (int i = tid; i < NF * NB; i += QTHREADS) {
        sRP[i] = g_rpq[i];
        sEW[i] = g_effw[i];
        sMW[i] = g_qmw[i];
    }
    if (tid < NB) sQB[tid] = qbias[tid];

    const int qbase = blockIdx.x * QPB;
    for (int i = tid; i < QPB * D; i += QTHREADS)
        sQn[i] = Q[(size_t)qbase * D + i];
    __syncthreads();

    {
        int q = tid >> 3, l8 = tid & 7;
        float s = 0.0f;
        #pragma unroll
        for (int j = 0; j < D / 8; j++) {
            float v = sQn[q * D + l8 + 8 * j];
            s = fmaf(v, v, s);
        }
        s += __shfl_down_sync(0xffffffffu, s, 4, 8);
        s += __shfl_down_sync(0xffffffffu, s, 2, 8);
        s += __shfl_down_sync(0xffffffffu, s, 1, 8);
        if (l8 == 0) sInv[q] = 1.0f / (sqrtf(s) + EPSF);
    }
    __syncthreads();
    for (int i = tid; i < QPB * D; i += QTHREADS)
        sQn[i] *= sInv[i >> 7];
    __syncthreads();
    for (int i = tid; i < QPB * NF; i += QTHREADS) {
        int q = i >> 6, f = i & 63;
        float a = sQn[q * D + 2 * f];
        float c = sQn[q * D + 2 * f + 1];
        sQmag[i] = sqrt_approx(fmaf(a, a, fmaf(c, c, EPSF)));
    }
    __syncthreads();

    const int b  = tid & 127;
    const int qg = tid >> 7;
    float acc[16];
    #pragma unroll
    for (int j = 0; j < 16; j++) acc[j] = 0.0f;

    for (int f = 0; f < NF; f++) {
        float2 rp = sRP[f * NB + b];
        float  ew = sEW[f * NB + b];
        float  mw = sMW[f * NB + b];
        #pragma unroll
        for (int j = 0; j < 16; j++) {
            int q = qg * 16 + j;
            float2 qp = *reinterpret_cast<const float2*>(sQn + q * D + 2 * f);
            float d0 = rp.x - qp.x;
            float d1 = rp.y - qp.y;
            float dist = sqrt_approx(fmaf(d0, d0, fmaf(d1, d1, EPSF)));
            acc[j] = fmaf(dist, ew, acc[j]);
            acc[j] = fmaf(sQmag[q * NF + f], mw, acc[j]);
        }
    }

    #pragma unroll
    for (int j = 0; j < 16; j++) {
        int q = qbase + qg * 16 + j;
        outq[(size_t)q * NB + b] = acc[j] + sQB[b];
    }
}

// ---------------------------------------------------------------------------
// Launch
// ---------------------------------------------------------------------------
extern "C" void kernel_launch(void* const* d_in, const int* in_sizes, int n_in,
                              void* d_out, int out_size)
{
    const float* Q      = (const float*)d_in[0];
    const float* Kmat   = (const float*)d_in[1];
    const float* angles = (const float*)d_in[2];
    const float* probes = (const float*)d_in[3];
    const float* kmw    = (const float*)d_in[4];
    const float* kbias  = (const float*)d_in[5];
    const float* qraw   = (const float*)d_in[6];
    const float* qmw    = (const float*)d_in[7];
    const float* qbias  = (const float*)d_in[8];
    float* out = (float*)d_out;

    const size_t smemQ = (size_t)(2 * NF * NB + NF * NB + NF * NB + QPB * D + QPB * NF
                                  + QPB + NB) * sizeof(float);

    cudaFuncSetAttribute(kpath_kernel, cudaFuncAttributeMaxDynamicSharedMemorySize, SMEMK_SZ);
    cudaFuncSetAttribute(qpath_kernel, cudaFuncAttributeMaxDynamicSharedMemorySize, (int)smemQ);

    prep_kernel<<<NB, NF>>>(angles, probes, kmw, qraw, qmw);
    kpath_kernel<<<NK / (TILE_M * TILES), KTHREADS, SMEMK_SZ>>>(Kmat, kbias, out);
    qpath_kernel<<<NQ / QPB, QTHREADS, smemQ>>>(Q, qbias, out + (size_t)NK * NB);
}

// round 9
// speedup vs baseline: 3.6436x; 1.0682x over previous
#include <cuda_runtime.h>
#include <cuda_fp16.h>
#include <cstdint>

// ---------------------------------------------------------------------------
// Problem constants
// ---------------------------------------------------------------------------
#define EPSF 1e-8f

constexpr int NQ = 8192;     // queries
constexpr int NK = 524288;   // keys
constexpr int D  = 128;      // head_dim
constexpr int NF = 64;       // num_freqs
constexpr int NB = 128;      // num_bins
constexpr int DT = 192;      // D + NF  (GEMM K-dimension)

constexpr int STRIDE = 200;                    // fp16 elems per row (400B -> conflict-free ldmatrix)
constexpr int WBUF_BYTES = 128 * STRIDE * 2;   // 51,200 B

// ---------------------------------------------------------------------------
// Device scratch (no allocations allowed)
// ---------------------------------------------------------------------------
__device__ __align__(16) __half g_Wh[128 * STRIDE];   // W fp16, [bin][k], stride 200
__device__ float2 g_rpq[NF * NB];    // rotated probe pairs, [f][b]
__device__ float  g_effw[NF * NB];   // -softplus(q_weights_raw), [f][b]
__device__ float  g_qmw[NF * NB];    // q_magnitude_weights, [f][b]

// ---------------------------------------------------------------------------
// Helpers
// ---------------------------------------------------------------------------
__device__ __forceinline__ float sqrt_approx(float x) {
    float y;
    asm("sqrt.approx.f32 %0, %1;" : "=f"(y) : "f"(x));
    return y;
}

__device__ __forceinline__ uint32_t packh2(float a, float b) {
    __half2 t = __floats2half2_rn(a, b);
    return *reinterpret_cast<uint32_t*>(&t);
}

__device__ __forceinline__ uint32_t smem_u32(const void* p) {
    uint32_t a;
    asm("{ .reg .u64 t; cvta.to.shared.u64 t, %1; cvt.u32.u64 %0, t; }" : "=r"(a) : "l"(p));
    return a;
}

__device__ __forceinline__ void ldm4(uint32_t* r, uint32_t addr) {
    asm volatile("ldmatrix.sync.aligned.m8n8.x4.shared.b16 {%0,%1,%2,%3}, [%4];"
        : "=r"(r[0]), "=r"(r[1]), "=r"(r[2]), "=r"(r[3]) : "r"(addr));
}

__device__ __forceinline__ void mma16816(float* c, const uint32_t* a, const uint32_t* b) {
    asm volatile("mma.sync.aligned.m16n8k16.row.col.f32.f16.f16.f32 "
        "{%0,%1,%2,%3}, {%4,%5,%6,%7}, {%8,%9}, {%0,%1,%2,%3};"
        : "+f"(c[0]), "+f"(c[1]), "+f"(c[2]), "+f"(c[3])
        : "r"(a[0]), "r"(a[1]), "r"(a[2]), "r"(a[3]), "r"(b[0]), "r"(b[1]));
}

// ---------------------------------------------------------------------------
// Prep kernel: one block per bin, 64 threads (one per freq)
// ---------------------------------------------------------------------------
__global__ void prep_kernel(const float* __restrict__ angles,
                            const float* __restrict__ probes,
                            const float* __restrict__ kmw,
                            const float* __restrict__ qraw,
                            const float* __restrict__ qmw)
{
    __shared__ float red[2];
    const int b = blockIdx.x;
    const int f = threadIdx.x;   // 0..63

    float p0 = probes[b * D + 2 * f];
    float p1 = probes[b * D + 2 * f + 1];
    float s = fmaf(p0, p0, p1 * p1);
    #pragma unroll
    for (int o = 16; o; o >>= 1) s += __shfl_xor_sync(0xffffffffu, s, o);
    if ((f & 31) == 0) red[f >> 5] = s;
    __syncthreads();
    float inv = 1.0f / (sqrtf(red[0] + red[1]) + EPSF);
    p0 *= inv; p1 *= inv;

    float a  = angles[f];
    float ca = cosf(a), sa = sinf(a);
    float r0 = p0 * ca - p1 * sa;
    float r1 = p0 * sa + p1 * ca;
    g_rpq[f * NB + b] = make_float2(r0, r1);

    g_Wh[b * STRIDE + 2 * f]     = __float2half_rn(r0);
    g_Wh[b * STRIDE + 2 * f + 1] = __float2half_rn(r1);
    g_Wh[b * STRIDE + D + f]     = __float2half_rn(kmw[b * NF + f]);
    if (f < 8) g_Wh[b * STRIDE + 192 + f] = __float2half_rn(0.f);

    float x  = qraw[b * NF + f];
    float sp = fmaxf(x, 0.0f) + log1pf(expf(-fabsf(x)));
    g_effw[f * NB + b] = -sp;
    g_qmw[f * NB + b]  = qmw[b * NF + f];
}

// ---------------------------------------------------------------------------
// Fused kernel: blocks [0, KBLOCKS) do the K-path GEMM; the rest do Q-path.
// ---------------------------------------------------------------------------
constexpr int TILE_M   = 128;
constexpr int KTHREADS = 512;
constexpr int TILES    = 4;
constexpr int KBLOCKS  = NK / (TILE_M * TILES);           // 1024
constexpr int FPT      = (TILE_M * (D / 4)) / KTHREADS;   // float4 per thread = 8

constexpr int QPB      = 64;
constexpr int QBLOCKS  = NQ / QPB;                        // 128

// kpath smem layout
constexpr int OFF_WH   = 0;
constexpr int OFF_A0   = OFF_WH + WBUF_BYTES;    //  51,200
constexpr int OFF_A1   = OFF_A0 + WBUF_BYTES;    // 102,400
constexpr int OFF_BIAS = OFF_A1 + WBUF_BYTES;    // 153,600
// qpath smem (floats): 16384 + 8192*3 + 4096 + 64 + 128 = 45,248 floats = 180,992 B
constexpr int SMEM_SZ  = 181248;

// ---- K path body -----------------------------------------------------------
__device__ __forceinline__ void kpath_body(char* smc, const float* __restrict__ Kmat,
                                           const float* __restrict__ kbias,
                                           float* __restrict__ out)
{
    const uint32_t base = smem_u32(smc);
    float* sBias = reinterpret_cast<float*>(smc + OFF_BIAS);

    const int tid  = threadIdx.x;
    const int lane = tid & 31;
    const int wid  = tid >> 5;
    const int wm   = (wid & 3) * 32;    // warp M offset
    const int wn   = (wid >> 2) * 32;   // warp N offset

    // W -> smem (layout already final)
    {
        const int4* gw = reinterpret_cast<const int4*>(g_Wh);
        int4* sw = reinterpret_cast<int4*>(smc + OFF_WH);
        for (int i = tid; i < WBUF_BYTES / 16; i += KTHREADS) sw[i] = gw[i];
    }
    if (tid < NB) sBias[tid] = kbias[tid];

    // ldmatrix lane base addresses
    const int aRow = wm + (lane & 7) + ((lane >> 3) & 1) * 8;
    const int aK   = ((lane >> 4) & 1) * 8;
    const uint32_t aFragOff = (uint32_t)(aRow * STRIDE + aK) * 2;
    const uint32_t aA[2] = { base + OFF_A0 + aFragOff, base + OFF_A1 + aFragOff };
    const int bRow = wn + (lane & 7) + ((lane >> 4) & 1) * 8;
    const int bK   = ((lane >> 3) & 1) * 8;
    const uint32_t bA = base + OFF_WH + (uint32_t)(bRow * STRIDE + bK) * 2;

    constexpr uint32_t MSTEP = 16 * STRIDE * 2;   // 16 rows in bytes

    const size_t blockRow0 = (size_t)blockIdx.x * TILES * TILE_M;
    const float4* K4base = reinterpret_cast<const float4*>(Kmat);

    // ---- Prologue: LDG tile0 -> regs, convert -> A0, LDG tile1 -> regs
    float4 pf[FPT];
    {
        const float4* g = K4base + blockRow0 * (D / 4);
        #pragma unroll
        for (int it = 0; it < FPT; it++) pf[it] = g[it * KTHREADS + tid];
    }
    #pragma unroll
    for (int it = 0; it < FPT; it++) {
        const int i = it * KTHREADS + tid;
        const int row = i >> 5, c4 = i & 31;
        float4 v = pf[it];
        const int e0 = row * STRIDE + 4 * c4;
        *reinterpret_cast<uint2*>(smc + OFF_A0 + 2 * e0) =
            make_uint2(packh2(v.x, v.y), packh2(v.z, v.w));
        float m0 = sqrt_approx(fmaf(v.x, v.x, fmaf(v.y, v.y, EPSF)));
        float m1 = sqrt_approx(fmaf(v.z, v.z, fmaf(v.w, v.w, EPSF)));
        const int em = row * STRIDE + D + 2 * c4;
        *reinterpret_cast<uint32_t*>(smc + OFF_A0 + 2 * em) = packh2(m0, m1);
    }
    {
        const float4* g = K4base + (blockRow0 + TILE_M) * (D / 4);
        #pragma unroll
        for (int it = 0; it < FPT; it++) pf[it] = g[it * KTHREADS + tid];
    }
    __syncthreads();   // W + bias + A0 visible to all

    for (int t = 0; t < TILES; t++) {
        const size_t rowBase = blockRow0 + (size_t)t * TILE_M;
        const bool doConv = (t + 1 < TILES);
        const bool doLdg  = (t + 2 < TILES);
        const uint32_t aCur = aA[t & 1];
        char* nxtBase = smc + OFF_A0 + ((t + 1) & 1) * WBUF_BYTES;
        const float4* gNext = K4base + (rowBase + 2 * TILE_M) * (D / 4);

        // ---- MMA mainloop with interleaved convert (kc<8) and LDG t+2 (kc>=8)
        float c[2][4][4];
        #pragma unroll
        for (int i = 0; i < 2; i++)
            #pragma unroll
            for (int j = 0; j < 4; j++)
                #pragma unroll
                for (int r = 0; r < 4; r++) c[i][j][r] = 0.0f;

        #pragma unroll
        for (int kc = 0; kc < DT / 16; kc++) {
            const uint32_t kB = (uint32_t)kc * 32;
            uint32_t af[2][4], bf[2][4];
            #pragma unroll
            for (int i = 0; i < 2; i++) ldm4(af[i], aCur + i * MSTEP + kB);
            #pragma unroll
            for (int jj = 0; jj < 2; jj++) ldm4(bf[jj], bA + jj * MSTEP + kB);
            #pragma unroll
            for (int i = 0; i < 2; i++)
                #pragma unroll
                for (int j = 0; j < 4; j++)
                    mma16816(c[i][j], af[i], &bf[j >> 1][(j & 1) * 2]);

            if (kc < FPT) {          // convert one pf chunk -> A_next
                if (doConv) {
                    const int i = kc * KTHREADS + (int)threadIdx.x;
                    const int row = i >> 5, c4 = i & 31;
                    float4 v = pf[kc];
                    const int e0 = row * STRIDE + 4 * c4;
                    *reinterpret_cast<uint2*>(nxtBase + 2 * e0) =
                        make_uint2(packh2(v.x, v.y), packh2(v.z, v.w));
                    float m0 = sqrt_approx(fmaf(v.x, v.x, fmaf(v.y, v.y, EPSF)));
                    float m1 = sqrt_approx(fmaf(v.z, v.z, fmaf(v.w, v.w, EPSF)));
                    const int em = row * STRIDE + D + 2 * c4;
                    *reinterpret_cast<uint32_t*>(nxtBase + 2 * em) = packh2(m0, m1);
                }
            } else {                 // LDG 2 chunks of tile t+2 -> pf
                if (doLdg) {
                    const int it0 = 2 * (kc - FPT);
                    pf[it0]     = gNext[it0 * KTHREADS + (int)threadIdx.x];
                    pf[it0 + 1] = gNext[(it0 + 1) * KTHREADS + (int)threadIdx.x];
                }
            }
        }

        // ---- Epilogue: bias + STG.64 from accumulators
        float2* out2 = reinterpret_cast<float2*>(out);
        const size_t r0 = rowBase + wm + (lane >> 2);
        #pragma unroll
        for (int j = 0; j < 4; j++) {
            const int col = wn + j * 8 + (lane & 3) * 2;
            const float bx = sBias[col], by = sBias[col + 1];
            const int ch = col >> 1;
            #pragma unroll
            for (int i = 0; i < 2; i++) {
                const size_t row = r0 + i * 16;
                float2 v0 = make_float2(c[i][j][0] + bx, c[i][j][1] + by);
                float2 v1 = make_float2(c[i][j][2] + bx, c[i][j][3] + by);
                out2[row * (NB / 2) + ch] = v0;
                out2[(row + 8) * (NB / 2) + ch] = v1;
            }
        }
        __syncthreads();   // A_next fully converted; A_cur reads done
    }
}

// ---- Q path body (64 queries per block, 512 threads) -----------------------
__device__ __forceinline__ void qpath_body(char* smc, const float* __restrict__ Q,
                                           const float* __restrict__ qbias,
                                           float* __restrict__ outq, int qb)
{
    float* smem = reinterpret_cast<float*>(smc);
    float2* sRP  = reinterpret_cast<float2*>(smem);      // 8192 float2
    float* sEW   = smem + 16384;                         // 8192
    float* sMW   = sEW + 8192;                           // 8192
    float* sQn   = sMW + 8192;                           // QPB*D = 8192
    float* sQmag = sQn + 8192;                           // QPB*NF = 4096
    float* sInv  = sQmag + 4096;                         // 64
    float* sQB   = sInv + 64;                            // 128

    const int tid = threadIdx.x;
    for (int i = tid; i < NF * NB; i += KTHREADS) {
        sRP[i] = g_rpq[i];
        sEW[i] = g_effw[i];
        sMW[i] = g_qmw[i];
    }
    if (tid < NB) sQB[tid] = qbias[tid];

    const int qbase = qb * QPB;
    for (int i = tid; i < QPB * D; i += KTHREADS)
        sQn[i] = Q[(size_t)qbase * D + i];
    __syncthreads();

    {   // L2 norms: 8 threads per query (512 = 64*8 exactly)
        int q = tid >> 3, l8 = tid & 7;
        float s = 0.0f;
        #pragma unroll
        for (int j = 0; j < D / 8; j++) {
            float v = sQn[q * D + l8 + 8 * j];
            s = fmaf(v, v, s);
        }
        s += __shfl_down_sync(0xffffffffu, s, 4, 8);
        s += __shfl_down_sync(0xffffffffu, s, 2, 8);
        s += __shfl_down_sync(0xffffffffu, s, 1, 8);
        if (l8 == 0) sInv[q] = 1.0f / (sqrtf(s) + EPSF);
    }
    __syncthreads();
    for (int i = tid; i < QPB * D; i += KTHREADS)
        sQn[i] *= sInv[i >> 7];
    __syncthreads();
    for (int i = tid; i < QPB * NF; i += KTHREADS) {
        int q = i >> 6, f = i & 63;
        float a = sQn[q * D + 2 * f];
        float c = sQn[q * D + 2 * f + 1];
        sQmag[i] = sqrt_approx(fmaf(a, a, fmaf(c, c, EPSF)));
    }
    __syncthreads();

    const int b  = tid & 127;
    const int qg = tid >> 7;    // 0..3, 16 queries each
    float acc[16];
    #pragma unroll
    for (int j = 0; j < 16; j++) acc[j] = 0.0f;

    for (int f = 0; f < NF; f++) {
        float2 rp = sRP[f * NB + b];
        float  ew = sEW[f * NB + b];
        float  mw = sMW[f * NB + b];
        #pragma unroll
        for (int j = 0; j < 16; j++) {
            int q = qg * 16 + j;
            float2 qp = *reinterpret_cast<const float2*>(sQn + q * D + 2 * f);
            float d0 = rp.x - qp.x;
            float d1 = rp.y - qp.y;
            float dist = sqrt_approx(fmaf(d0, d0, fmaf(d1, d1, EPSF)));
            acc[j] = fmaf(dist, ew, acc[j]);
            acc[j] = fmaf(sQmag[q * NF + f], mw, acc[j]);
        }
    }

    #pragma unroll
    for (int j = 0; j < 16; j++) {
        int q = qbase + qg * 16 + j;
        outq[(size_t)q * NB + b] = acc[j] + sQB[b];
    }
}

// ---- Fused kernel -----------------------------------------------------------
__global__ void __launch_bounds__(KTHREADS, 1)
fused_kernel(const float* __restrict__ Kmat,
             const float* __restrict__ kbias,
             const float* __restrict__ Q,
             const float* __restrict__ qbias,
             float* __restrict__ out)
{
    extern __shared__ char smc[];
    if (blockIdx.x < KBLOCKS) {
        kpath_body(smc, Kmat, kbias, out);
    } else {
        qpath_body(smc, Q, qbias, out + (size_t)NK * NB, blockIdx.x - KBLOCKS);
    }
}

// ---------------------------------------------------------------------------
// Launch
// ---------------------------------------------------------------------------
extern "C" void kernel_launch(void* const* d_in, const int* in_sizes, int n_in,
                              void* d_out, int out_size)
{
    const float* Q      = (const float*)d_in[0];
    const float* Kmat   = (const float*)d_in[1];
    const float* angles = (const float*)d_in[2];
    const float* probes = (const float*)d_in[3];
    const float* kmw    = (const float*)d_in[4];
    const float* kbias  = (const float*)d_in[5];
    const float* qraw   = (const float*)d_in[6];
    const float* qmw    = (const float*)d_in[7];
    const float* qbias  = (const float*)d_in[8];
    float* out = (float*)d_out;

    cudaFuncSetAttribute(fused_kernel, cudaFuncAttributeMaxDynamicSharedMemorySize, SMEM_SZ);

    prep_kernel<<<NB, NF>>>(angles, probes, kmw, qraw, qmw);
    fused_kernel<<<KBLOCKS + QBLOCKS, KTHREADS, SMEM_SZ>>>(Kmat, kbias, Q, qbias, out);
}